// round 1
// baseline (speedup 1.0000x reference)
#include <cuda_runtime.h>
#include <cstdint>

#define NUM_T 2048
#define NUM_H 1024
#define NUM_I 1024
#define NUM_E 8
#define NROWS (NUM_T * 2)

// ---------------- device scratch (no allocations allowed) ----------------
__device__ int   d_count[NUM_E];
__device__ int   d_offset[NUM_E + 1];
__device__ int   d_cursor[NUM_E];
__device__ int   d_topk_id[NUM_T * 2];
__device__ float d_topk_w[NUM_T * 2];
__device__ int   d_row_token[NROWS];
__device__ float d_row_weight[NROWS];
__device__ float d_gu[(size_t)NROWS * (2 * NUM_I)];   // 32 MB
__device__ float d_inter[(size_t)NROWS * NUM_I];      // 16 MB

// ---------------- small kernels ----------------
__global__ void init_kernel(float* out, int n4) {
    int idx = blockIdx.x * blockDim.x + threadIdx.x;
    if (idx < n4) reinterpret_cast<float4*>(out)[idx] = make_float4(0.f, 0.f, 0.f, 0.f);
    if (blockIdx.x == 0 && threadIdx.x < NUM_E) {
        d_count[threadIdx.x]  = 0;
        d_cursor[threadIdx.x] = 0;
    }
}

__global__ void router_kernel(const float* __restrict__ logits) {
    int t = blockIdx.x * blockDim.x + threadIdx.x;
    if (t >= NUM_T) return;
    float l[NUM_E];
#pragma unroll
    for (int e = 0; e < NUM_E; e++) l[e] = logits[t * NUM_E + e];
    int i0 = 0; float v0 = l[0];
#pragma unroll
    for (int e = 1; e < NUM_E; e++) if (l[e] > v0) { v0 = l[e]; i0 = e; }
    int i1 = -1; float v1 = -1e30f;
#pragma unroll
    for (int e = 0; e < NUM_E; e++) if (e != i0 && l[e] > v1) { v1 = l[e]; i1 = e; }
    // renormalized top-2 softmax: denominator cancels
    float z  = expf(v1 - v0);
    float w0 = 1.0f / (1.0f + z);
    float w1 = z / (1.0f + z);
    d_topk_id[t * 2] = i0; d_topk_id[t * 2 + 1] = i1;
    d_topk_w[t * 2]  = w0; d_topk_w[t * 2 + 1]  = w1;
    atomicAdd(&d_count[i0], 1);
    atomicAdd(&d_count[i1], 1);
}

__global__ void scan_kernel() {
    d_offset[0] = 0;
    for (int e = 0; e < NUM_E; e++) d_offset[e + 1] = d_offset[e] + d_count[e];
}

__global__ void assign_kernel() {
    int t = blockIdx.x * blockDim.x + threadIdx.x;
    if (t >= NUM_T) return;
#pragma unroll
    for (int k = 0; k < 2; k++) {
        int e   = d_topk_id[t * 2 + k];
        int pos = atomicAdd(&d_cursor[e], 1);
        int row = d_offset[e] + pos;
        d_row_token[row]  = t;
        d_row_weight[row] = d_topk_w[t * 2 + k];
    }
}

__global__ void swiglu_kernel() {
    int r = blockIdx.x;
    int i = threadIdx.x * 4;
    const float* gp = d_gu + (size_t)r * (2 * NUM_I);
    float4 gv = *reinterpret_cast<const float4*>(gp + i);
    float4 uv = *reinterpret_cast<const float4*>(gp + NUM_I + i);
    float4 o;
    o.x = gv.x / (1.f + expf(-gv.x)) * uv.x;
    o.y = gv.y / (1.f + expf(-gv.y)) * uv.y;
    o.z = gv.z / (1.f + expf(-gv.z)) * uv.z;
    o.w = gv.w / (1.f + expf(-gv.w)) * uv.w;
    *reinterpret_cast<float4*>(d_inter + (size_t)r * NUM_I + i) = o;
}

// ---------------- tf32 mma helpers ----------------
__device__ __forceinline__ uint32_t f2tf(float f) {
    uint32_t u;
    asm("cvt.rna.tf32.f32 %0, %1;" : "=r"(u) : "f"(f));
    return u;
}

__device__ __forceinline__ void mma8(float* c, const uint32_t* a, const uint32_t* b) {
    asm volatile(
        "mma.sync.aligned.m16n8k8.row.col.f32.tf32.tf32.f32 "
        "{%0,%1,%2,%3}, {%4,%5,%6,%7}, {%8,%9}, {%0,%1,%2,%3};"
        : "+f"(c[0]), "+f"(c[1]), "+f"(c[2]), "+f"(c[3])
        : "r"(a[0]), "r"(a[1]), "r"(a[2]), "r"(a[3]), "r"(b[0]), "r"(b[1]));
}

// ---------------- grouped GEMM ----------------
// G2=false: C[row, 0..N) = x[token(row)] @ w13[e]           (N = 2048, K = 1024) -> d_gu
// G2=true : out[token] += w * (d_inter[row] @ w2[e])        (N = 1024, K = 1024) -> atomicAdd
template <bool G2, int N>
__global__ void __launch_bounds__(256)
moe_gemm(const float* __restrict__ A, const float* __restrict__ Bw, float* __restrict__ out) {
    const int e   = blockIdx.y >> 4;
    const int mt  = blockIdx.y & 15;
    const int cnt = d_count[e];
    const int m0  = mt * 128;
    if (m0 >= cnt) return;
    const int off = d_offset[e];
    const int n0  = blockIdx.x * 128;

    __shared__ uint32_t As[128 * 20];  // [m][k] stride 20 -> conflict-free frag loads
    __shared__ uint32_t Bs[16 * 136];  // [k][n] stride 136 -> conflict-free frag loads

    const int tid   = threadIdx.x;
    const int lane  = tid & 31;
    const int wid   = tid >> 5;
    const int warpM = (wid >> 2) * 64;
    const int warpN = (wid & 3) * 32;
    const int gq    = lane >> 2;
    const int tg    = lane & 3;

    // A tile loaders: thread -> rows (ar0, ar0+64), 4 consecutive k at aq0
    const int ar0 = tid >> 2;
    const int aq0 = (tid & 3) * 4;
    const bool av0 = (m0 + ar0) < cnt;
    const bool av1 = (m0 + ar0 + 64) < cnt;

    const float* Arow0;
    const float* Arow1;
    if (G2) {
        Arow0 = d_inter + (size_t)(off + m0 + ar0) * NUM_I;
        Arow1 = d_inter + (size_t)(off + m0 + ar0 + 64) * NUM_I;
    } else {
        int t0 = av0 ? d_row_token[off + m0 + ar0] : 0;
        int t1 = av1 ? d_row_token[off + m0 + ar0 + 64] : 0;
        Arow0 = A + (size_t)t0 * NUM_H;
        Arow1 = A + (size_t)t1 * NUM_H;
    }

    // B tile loaders: thread -> k rows (bk0, bk0+8), 4 consecutive n at bn0
    const int bk0 = tid >> 5;
    const int bn0 = (tid & 31) * 4;
    const float* Bbase = Bw + (size_t)e * 1024 * N + n0;

    float acc[4][4][4];
#pragma unroll
    for (int i = 0; i < 4; i++)
#pragma unroll
        for (int j = 0; j < 4; j++)
#pragma unroll
            for (int q = 0; q < 4; q++) acc[i][j][q] = 0.f;

    const float4 z4 = make_float4(0.f, 0.f, 0.f, 0.f);
    float4 xa0, xa1, xb0, xb1;

    // prefetch k-tile 0
    xa0 = av0 ? *reinterpret_cast<const float4*>(Arow0 + aq0) : z4;
    xa1 = av1 ? *reinterpret_cast<const float4*>(Arow1 + aq0) : z4;
    xb0 = *reinterpret_cast<const float4*>(Bbase + (size_t)bk0 * N + bn0);
    xb1 = *reinterpret_cast<const float4*>(Bbase + (size_t)(bk0 + 8) * N + bn0);

    const int KTILES = 1024 / 16;
    for (int kt = 0; kt < KTILES; kt++) {
        // stage (fp32 -> tf32) into smem
        uint4 u;
        u.x = f2tf(xa0.x); u.y = f2tf(xa0.y); u.z = f2tf(xa0.z); u.w = f2tf(xa0.w);
        *reinterpret_cast<uint4*>(&As[ar0 * 20 + aq0]) = u;
        u.x = f2tf(xa1.x); u.y = f2tf(xa1.y); u.z = f2tf(xa1.z); u.w = f2tf(xa1.w);
        *reinterpret_cast<uint4*>(&As[(ar0 + 64) * 20 + aq0]) = u;
        u.x = f2tf(xb0.x); u.y = f2tf(xb0.y); u.z = f2tf(xb0.z); u.w = f2tf(xb0.w);
        *reinterpret_cast<uint4*>(&Bs[bk0 * 136 + bn0]) = u;
        u.x = f2tf(xb1.x); u.y = f2tf(xb1.y); u.z = f2tf(xb1.z); u.w = f2tf(xb1.w);
        *reinterpret_cast<uint4*>(&Bs[(bk0 + 8) * 136 + bn0]) = u;
        __syncthreads();

        // prefetch next k-tile (overlaps with mma below)
        if (kt + 1 < KTILES) {
            int k = (kt + 1) * 16;
            xa0 = av0 ? *reinterpret_cast<const float4*>(Arow0 + k + aq0) : z4;
            xa1 = av1 ? *reinterpret_cast<const float4*>(Arow1 + k + aq0) : z4;
            xb0 = *reinterpret_cast<const float4*>(Bbase + (size_t)(k + bk0) * N + bn0);
            xb1 = *reinterpret_cast<const float4*>(Bbase + (size_t)(k + bk0 + 8) * N + bn0);
        }

#pragma unroll
        for (int kk = 0; kk < 16; kk += 8) {
            uint32_t af[4][4];
#pragma unroll
            for (int i = 0; i < 4; i++) {
                int m = warpM + i * 16 + gq;
                af[i][0] = As[m * 20 + kk + tg];
                af[i][1] = As[(m + 8) * 20 + kk + tg];
                af[i][2] = As[m * 20 + kk + tg + 4];
                af[i][3] = As[(m + 8) * 20 + kk + tg + 4];
            }
            uint32_t bf[4][2];
#pragma unroll
            for (int j = 0; j < 4; j++) {
                int n = warpN + j * 8 + gq;
                bf[j][0] = Bs[(kk + tg) * 136 + n];
                bf[j][1] = Bs[(kk + tg + 4) * 136 + n];
            }
#pragma unroll
            for (int i = 0; i < 4; i++)
#pragma unroll
                for (int j = 0; j < 4; j++) mma8(acc[i][j], af[i], bf[j]);
        }
        __syncthreads();
    }

    // ---------------- epilogue ----------------
#pragma unroll
    for (int i = 0; i < 4; i++) {
        int mlo = m0 + warpM + i * 16 + gq;
        int mhi = mlo + 8;
        if (!G2) {
#pragma unroll
            for (int j = 0; j < 4; j++) {
                int c = n0 + warpN + j * 8 + 2 * tg;
                if (mlo < cnt) {
                    float* p = d_gu + (size_t)(off + mlo) * (2 * NUM_I) + c;
                    p[0] = acc[i][j][0]; p[1] = acc[i][j][1];
                }
                if (mhi < cnt) {
                    float* p = d_gu + (size_t)(off + mhi) * (2 * NUM_I) + c;
                    p[0] = acc[i][j][2]; p[1] = acc[i][j][3];
                }
            }
        } else {
            float wlo = 0.f, whi = 0.f; int tlo = 0, thi = 0;
            if (mlo < cnt) { wlo = d_row_weight[off + mlo]; tlo = d_row_token[off + mlo]; }
            if (mhi < cnt) { whi = d_row_weight[off + mhi]; thi = d_row_token[off + mhi]; }
#pragma unroll
            for (int j = 0; j < 4; j++) {
                int c = n0 + warpN + j * 8 + 2 * tg;
                if (mlo < cnt) {
                    float* p = out + (size_t)tlo * NUM_H + c;
                    atomicAdd(p,     wlo * acc[i][j][0]);
                    atomicAdd(p + 1, wlo * acc[i][j][1]);
                }
                if (mhi < cnt) {
                    float* p = out + (size_t)thi * NUM_H + c;
                    atomicAdd(p,     whi * acc[i][j][2]);
                    atomicAdd(p + 1, whi * acc[i][j][3]);
                }
            }
        }
    }
}

// ---------------- launch ----------------
extern "C" void kernel_launch(void* const* d_in, const int* in_sizes, int n_in,
                              void* d_out, int out_size) {
    const float* x      = (const float*)d_in[0];
    const float* logits = (const float*)d_in[1];
    const float* w13    = (const float*)d_in[2];
    const float* w2     = (const float*)d_in[3];
    float* out = (float*)d_out;

    init_kernel<<<2048, 256>>>(out, (NUM_T * NUM_H) / 4);
    router_kernel<<<NUM_T / 256, 256>>>(logits);
    scan_kernel<<<1, 1>>>();
    assign_kernel<<<NUM_T / 256, 256>>>();
    // GEMM1: gu = gather(x) @ w13[e]   (N = 2048)
    moe_gemm<false, 2 * NUM_I><<<dim3((2 * NUM_I) / 128, NUM_E * 16), 256>>>(x, w13, nullptr);
    swiglu_kernel<<<NROWS, 256>>>();
    // GEMM2: out[token] += w * inter @ w2[e]   (N = 1024)
    moe_gemm<true, NUM_H><<<dim3(NUM_H / 128, NUM_E * 16), 256>>>(nullptr, w2, out);
}

// round 3
// speedup vs baseline: 1.6960x; 1.6960x over previous
#include <cuda_runtime.h>
#include <cuda_fp16.h>
#include <cstdint>

#define NUM_T 2048
#define NUM_H 1024
#define NUM_I 1024
#define NUM_E 8
#define NROWS (NUM_T * 2)

#define BM 128
#define BN 128
#define BK 32
#define KTILES 32          // 1024 / BK
#define STAGES 4
#define A_STRIDE 40        // halves; 80B rows -> conflict-free LDSM
#define B_STRIDE 136       // halves; 272B rows -> conflict-free LDSM.trans
#define A_BYTES (BM * A_STRIDE * 2)          // 10240
#define B_BYTES (BK * B_STRIDE * 2)          // 8704
#define STAGE_BYTES (A_BYTES + B_BYTES)      // 18944 (128B aligned)
#define SMEM_GEMM (STAGES * STAGE_BYTES)     // 75776

// ---------------- device scratch (static: no allocations allowed) ----------------
__device__ int    d_count[NUM_E];
__device__ int    d_offset[NUM_E + 1];
__device__ int    d_cursor[NUM_E];
__device__ int    d_topk_id[NROWS];
__device__ float  d_topk_w[NROWS];
__device__ int    d_row_token[NROWS];
__device__ float  d_row_weight[NROWS];

__device__ __half d_w13h[(size_t)NUM_E * 1024 * 2048];   // [E][K=1024][N=2048] fp16, 32MB
__device__ __half d_w2h [(size_t)NUM_E * 1024 * 1024];   // [E][K=1024][N=1024] fp16, 16MB
__device__ __half d_x16 [(size_t)NUM_T * 1024];          // tokens fp16, 4MB
__device__ float  d_gu  [(size_t)NROWS * 2048];          // GEMM1 out fp32, 32MB
__device__ __half d_inter[(size_t)NROWS * 1024];         // swiglu out fp16, 8MB

// ---------------- ptx helpers ----------------
__device__ __forceinline__ uint32_t smem_u32(const void* p) {
    uint32_t a;
    asm("{ .reg .u64 t; cvta.to.shared.u64 t, %1; cvt.u32.u64 %0, t; }" : "=r"(a) : "l"(p));
    return a;
}

__device__ __forceinline__ void cpa16(uint32_t dst, const void* src, uint32_t srcbytes) {
    asm volatile("cp.async.cg.shared.global [%0], [%1], 16, %2;"
                 :: "r"(dst), "l"(src), "r"(srcbytes));
}
__device__ __forceinline__ void cpa_commit() { asm volatile("cp.async.commit_group;" ::: "memory"); }

__device__ __forceinline__ void ldsm_x4(uint32_t* r, uint32_t addr) {
    asm volatile("ldmatrix.sync.aligned.m8n8.x4.shared.b16 {%0,%1,%2,%3}, [%4];"
                 : "=r"(r[0]), "=r"(r[1]), "=r"(r[2]), "=r"(r[3]) : "r"(addr));
}
__device__ __forceinline__ void ldsm_x4t(uint32_t* r, uint32_t addr) {
    asm volatile("ldmatrix.sync.aligned.m8n8.x4.trans.shared.b16 {%0,%1,%2,%3}, [%4];"
                 : "=r"(r[0]), "=r"(r[1]), "=r"(r[2]), "=r"(r[3]) : "r"(addr));
}

__device__ __forceinline__ void hmma(float* c, const uint32_t* a, const uint32_t* b) {
    asm volatile(
        "mma.sync.aligned.m16n8k16.row.col.f32.f16.f16.f32 "
        "{%0,%1,%2,%3}, {%4,%5,%6,%7}, {%8,%9}, {%0,%1,%2,%3};"
        : "+f"(c[0]), "+f"(c[1]), "+f"(c[2]), "+f"(c[3])
        : "r"(a[0]), "r"(a[1]), "r"(a[2]), "r"(a[3]), "r"(b[0]), "r"(b[1]));
}

// ---------------- prep: fp32 -> fp16 converts + out zero + counter clear ----------------
__device__ __forceinline__ void cvt4(__half* dst, const float* src, int i) {
    float4 v = reinterpret_cast<const float4*>(src)[i];
    uint2 h;
    h.x = __half2_raw(__halves2half2(__float2half_rn(v.x), __float2half_rn(v.y))).x |
          ((uint32_t)0);  // pack via reinterpret below
    __half2 p0 = __halves2half2(__float2half_rn(v.x), __float2half_rn(v.y));
    __half2 p1 = __halves2half2(__float2half_rn(v.z), __float2half_rn(v.w));
    h.x = *reinterpret_cast<uint32_t*>(&p0);
    h.y = *reinterpret_cast<uint32_t*>(&p1);
    reinterpret_cast<uint2*>(dst)[i] = h;
}

__global__ void prep_kernel(const float* __restrict__ x, const float* __restrict__ w13,
                            const float* __restrict__ w2, float* __restrict__ out) {
    const int stride = gridDim.x * blockDim.x;
    const int tid = blockIdx.x * blockDim.x + threadIdx.x;
    for (int i = tid; i < (NUM_E * 1024 * 2048) / 4; i += stride) cvt4(d_w13h, w13, i);
    for (int i = tid; i < (NUM_E * 1024 * 1024) / 4; i += stride) cvt4(d_w2h, w2, i);
    for (int i = tid; i < (NUM_T * 1024) / 4; i += stride) cvt4(d_x16, x, i);
    const float4 z = make_float4(0.f, 0.f, 0.f, 0.f);
    for (int i = tid; i < (NUM_T * NUM_H) / 4; i += stride) reinterpret_cast<float4*>(out)[i] = z;
    if (tid < NUM_E) { d_count[tid] = 0; d_cursor[tid] = 0; }
}

// ---------------- routing ----------------
__global__ void router_kernel(const float* __restrict__ logits) {
    __shared__ int cnt[NUM_E];
    if (threadIdx.x < NUM_E) cnt[threadIdx.x] = 0;
    __syncthreads();
    int t = blockIdx.x * blockDim.x + threadIdx.x;
    if (t < NUM_T) {
        float l[NUM_E];
#pragma unroll
        for (int e = 0; e < NUM_E; e++) l[e] = logits[t * NUM_E + e];
        int i0 = 0; float v0 = l[0];
#pragma unroll
        for (int e = 1; e < NUM_E; e++) if (l[e] > v0) { v0 = l[e]; i0 = e; }
        int i1 = -1; float v1 = -1e30f;
#pragma unroll
        for (int e = 0; e < NUM_E; e++) if (e != i0 && l[e] > v1) { v1 = l[e]; i1 = e; }
        float z  = expf(v1 - v0);
        float w0 = 1.0f / (1.0f + z);
        d_topk_id[t * 2] = i0; d_topk_id[t * 2 + 1] = i1;
        d_topk_w[t * 2]  = w0; d_topk_w[t * 2 + 1]  = 1.0f - w0;
        atomicAdd(&cnt[i0], 1);
        atomicAdd(&cnt[i1], 1);
    }
    __syncthreads();
    if (threadIdx.x < NUM_E) atomicAdd(&d_count[threadIdx.x], cnt[threadIdx.x]);
}

__global__ void scan_kernel() {
    d_offset[0] = 0;
    for (int e = 0; e < NUM_E; e++) d_offset[e + 1] = d_offset[e] + d_count[e];
}

__global__ void assign_kernel() {
    __shared__ int cnt[NUM_E], base[NUM_E];
    if (threadIdx.x < NUM_E) cnt[threadIdx.x] = 0;
    __syncthreads();
    int t = blockIdx.x * blockDim.x + threadIdx.x;
    int e0 = 0, e1 = 0, p0 = 0, p1 = 0;
    if (t < NUM_T) {
        e0 = d_topk_id[t * 2];     e1 = d_topk_id[t * 2 + 1];
        p0 = atomicAdd(&cnt[e0], 1);
        p1 = atomicAdd(&cnt[e1], 1);
    }
    __syncthreads();
    if (threadIdx.x < NUM_E) base[threadIdx.x] = atomicAdd(&d_cursor[threadIdx.x], cnt[threadIdx.x]);
    __syncthreads();
    if (t < NUM_T) {
        int r0 = d_offset[e0] + base[e0] + p0;
        int r1 = d_offset[e1] + base[e1] + p1;
        d_row_token[r0] = t;  d_row_weight[r0] = d_topk_w[t * 2];
        d_row_token[r1] = t;  d_row_weight[r1] = d_topk_w[t * 2 + 1];
    }
}

// ---------------- swiglu: d_gu fp32 -> d_inter fp16 ----------------
__global__ void swiglu_kernel() {
    int r = blockIdx.x;
    int i = threadIdx.x * 4;
    const float* gp = d_gu + (size_t)r * 2048;
    float4 g = *reinterpret_cast<const float4*>(gp + i);
    float4 u = *reinterpret_cast<const float4*>(gp + 1024 + i);
    float o0 = g.x / (1.f + expf(-g.x)) * u.x;
    float o1 = g.y / (1.f + expf(-g.y)) * u.y;
    float o2 = g.z / (1.f + expf(-g.z)) * u.z;
    float o3 = g.w / (1.f + expf(-g.w)) * u.w;
    __half2 p0 = __halves2half2(__float2half_rn(o0), __float2half_rn(o1));
    __half2 p1 = __halves2half2(__float2half_rn(o2), __float2half_rn(o3));
    uint2 h;
    h.x = *reinterpret_cast<uint32_t*>(&p0);
    h.y = *reinterpret_cast<uint32_t*>(&p1);
    *reinterpret_cast<uint2*>(d_inter + (size_t)r * 1024 + i) = h;
}

// ---------------- grouped GEMM (fp16 mma.sync + ldmatrix + 4-stage cp.async) ----------------
// G2=false: d_gu[row, n0..n0+BN) = x16[token(row)] @ w13h[e]   (NGLOB = 2048)
// G2=true : out[token] += w * (d_inter[row] @ w2h[e])          (NGLOB = 1024)
template <bool G2, int NGLOB>
__global__ void __launch_bounds__(256) gemm_cl(float* __restrict__ outp) {
    extern __shared__ __align__(128) char smem[];
    const uint32_t sb = smem_u32(smem);
    const int tid = threadIdx.x, wid = tid >> 5, lane = tid & 31;

    const int e   = blockIdx.y >> 4;
    const int mt  = blockIdx.y & 15;
    const int cnt = d_count[e];
    const int m0  = mt * BM;
    if (m0 >= cnt) return;
    const int off  = d_offset[e];
    const int n0   = blockIdx.x * BN;
    const int row0 = off + m0;

    const __half* Bw = (G2 ? d_w2h : d_w13h) + (size_t)e * 1024 * NGLOB;

    // A loader: thread covers rows r0a and r0a+64, 16B segment s0 (8 halves)
    const int r0a = tid >> 2;
    const int s0  = tid & 3;
    const bool v0 = (m0 + r0a) < cnt;
    const bool v1 = (m0 + r0a + 64) < cnt;
    const __half *Arow0, *Arow1;
    if (G2) {
        int g0 = min(row0 + r0a, NROWS - 1);
        int g1 = min(row0 + r0a + 64, NROWS - 1);
        Arow0 = d_inter + (size_t)g0 * 1024;
        Arow1 = d_inter + (size_t)g1 * 1024;
    } else {
        int g0 = v0 ? d_row_token[row0 + r0a] : 0;
        int g1 = v1 ? d_row_token[row0 + r0a + 64] : 0;
        Arow0 = d_x16 + (size_t)g0 * 1024;
        Arow1 = d_x16 + (size_t)g1 * 1024;
    }
    // B loader: thread covers k-rows kr0 and kr0+16, 16B segment sB
    const int kr0 = tid >> 4;
    const int sB  = tid & 15;

    auto load_stage = [&](int stg, int k0) {
        uint32_t base = sb + (uint32_t)stg * STAGE_BYTES;
        uint32_t da = base + (uint32_t)(r0a * 80 + s0 * 16);
        cpa16(da,            Arow0 + k0 + s0 * 8, v0 ? 16u : 0u);
        cpa16(da + 64 * 80,  Arow1 + k0 + s0 * 8, v1 ? 16u : 0u);
        uint32_t db = base + A_BYTES + (uint32_t)(kr0 * 272 + sB * 16);
        cpa16(db,             Bw + (size_t)(k0 + kr0) * NGLOB + n0 + sB * 8, 16u);
        cpa16(db + 16 * 272,  Bw + (size_t)(k0 + kr0 + 16) * NGLOB + n0 + sB * 8, 16u);
    };

    const int warpM = (wid >> 2) * 64;
    const int warpN = (wid & 3) * 32;

    float acc[4][4][4];
#pragma unroll
    for (int i = 0; i < 4; i++)
#pragma unroll
        for (int j = 0; j < 4; j++)
#pragma unroll
            for (int q = 0; q < 4; q++) acc[i][j][q] = 0.f;

    // lane-dependent ldmatrix offsets (stage-invariant parts)
    const int a_row = lane & 15;           // + warpM + i*16
    const int a_col = (lane >> 4) << 3;    // + kk
    const int b_row = (lane & 7) + (((lane >> 3) & 1) << 3);  // + kk
    const int b_col = (lane >> 4) << 3;    // + warpN + j2*16

#pragma unroll
    for (int s = 0; s < STAGES - 1; s++) { load_stage(s, s * BK); cpa_commit(); }

    for (int kt = 0; kt < KTILES; kt++) {
        asm volatile("cp.async.wait_group %0;" :: "n"(STAGES - 2));
        __syncthreads();
        int nk = kt + STAGES - 1;
        if (nk < KTILES) load_stage(nk & (STAGES - 1), nk * BK);
        cpa_commit();

        uint32_t As = sb + (uint32_t)(kt & (STAGES - 1)) * STAGE_BYTES;
        uint32_t Bs = As + A_BYTES;
#pragma unroll
        for (int kk = 0; kk < BK; kk += 16) {
            uint32_t af[4][4], bt[2][4];
#pragma unroll
            for (int i = 0; i < 4; i++)
                ldsm_x4(af[i], As + (uint32_t)((warpM + i * 16 + a_row) * 80 + (kk + a_col) * 2));
#pragma unroll
            for (int j2 = 0; j2 < 2; j2++)
                ldsm_x4t(bt[j2], Bs + (uint32_t)((kk + b_row) * 272 + (warpN + j2 * 16 + b_col) * 2));
#pragma unroll
            for (int i = 0; i < 4; i++)
#pragma unroll
                for (int j = 0; j < 4; j++)
                    hmma(acc[i][j], af[i], &bt[j >> 1][(j & 1) * 2]);
        }
    }

    // ---------------- epilogue ----------------
    const int gq = lane >> 2, tg = lane & 3;
#pragma unroll
    for (int i = 0; i < 4; i++) {
        int mlo = m0 + warpM + i * 16 + gq;
        int mhi = mlo + 8;
        if (!G2) {
#pragma unroll
            for (int j = 0; j < 4; j++) {
                int c = n0 + warpN + j * 8 + 2 * tg;
                if (mlo < cnt) {
                    float* p = d_gu + (size_t)(off + mlo) * 2048 + c;
                    p[0] = acc[i][j][0]; p[1] = acc[i][j][1];
                }
                if (mhi < cnt) {
                    float* p = d_gu + (size_t)(off + mhi) * 2048 + c;
                    p[0] = acc[i][j][2]; p[1] = acc[i][j][3];
                }
            }
        } else {
            float wlo = 0.f, whi = 0.f; int tlo = 0, thi = 0;
            if (mlo < cnt) { wlo = d_row_weight[off + mlo]; tlo = d_row_token[off + mlo]; }
            if (mhi < cnt) { whi = d_row_weight[off + mhi]; thi = d_row_token[off + mhi]; }
#pragma unroll
            for (int j = 0; j < 4; j++) {
                int c = n0 + warpN + j * 8 + 2 * tg;
                if (mlo < cnt) {
                    float* p = outp + (size_t)tlo * NUM_H + c;
                    atomicAdd(p,     wlo * acc[i][j][0]);
                    atomicAdd(p + 1, wlo * acc[i][j][1]);
                }
                if (mhi < cnt) {
                    float* p = outp + (size_t)thi * NUM_H + c;
                    atomicAdd(p,     whi * acc[i][j][2]);
                    atomicAdd(p + 1, whi * acc[i][j][3]);
                }
            }
        }
    }
}

// ---------------- launch ----------------
extern "C" void kernel_launch(void* const* d_in, const int* in_sizes, int n_in,
                              void* d_out, int out_size) {
    const float* x      = (const float*)d_in[0];
    const float* logits = (const float*)d_in[1];
    const float* w13    = (const float*)d_in[2];
    const float* w2     = (const float*)d_in[3];
    float* out = (float*)d_out;

    static bool attr_set = false;
    if (!attr_set) {
        cudaFuncSetAttribute(gemm_cl<false, 2048>, cudaFuncAttributeMaxDynamicSharedMemorySize, SMEM_GEMM);
        cudaFuncSetAttribute(gemm_cl<true, 1024>,  cudaFuncAttributeMaxDynamicSharedMemorySize, SMEM_GEMM);
        attr_set = true;
    }

    prep_kernel<<<1024, 256>>>(x, w13, w2, out);
    router_kernel<<<NUM_T / 256, 256>>>(logits);
    scan_kernel<<<1, 1>>>();
    assign_kernel<<<NUM_T / 256, 256>>>();
    gemm_cl<false, 2048><<<dim3(2048 / BN, NUM_E * 16), 256, SMEM_GEMM>>>(nullptr);
    swiglu_kernel<<<NROWS, 256>>>();
    gemm_cl<true, 1024><<<dim3(1024 / BN, NUM_E * 16), 256, SMEM_GEMM>>>(out);
}

// round 5
// speedup vs baseline: 1.7675x; 1.0422x over previous
#include <cuda_runtime.h>
#include <cuda_fp16.h>
#include <cstdint>

#define NUM_T 2048
#define NUM_H 1024
#define NUM_I 1024
#define NUM_E 8
#define NROWS (NUM_T * 2)

#define BM 128
#define BN 128
#define BK 32
#define KTILES 32          // 1024 / BK
#define STAGES 4
#define A_STRIDE 40        // halves; 80B rows -> conflict-free LDSM
#define B_STRIDE 136       // halves; 272B rows -> conflict-free LDSM.trans
#define A_BYTES (BM * A_STRIDE * 2)          // 10240
#define B_BYTES (BK * B_STRIDE * 2)          // 8704
#define STAGE_BYTES (A_BYTES + B_BYTES)      // 18944
#define SMEM_GEMM (STAGES * STAGE_BYTES)     // 75776  (>= 128*132*4 epilogue buffer)

// ---------------- device scratch (static: no allocations allowed) ----------------
__device__ int    d_count[NUM_E];
__device__ int    d_offset[NUM_E + 1];
__device__ float  d_topk_w[NROWS];
__device__ int    d_tok_row[NROWS];      // token -> its 2 rows
__device__ int    d_row_token[NROWS];    // row -> token

__device__ __half d_w13h[(size_t)NUM_E * 1024 * 2048];   // interleaved cols, 32MB
__device__ __half d_w2h [(size_t)NUM_E * 1024 * 1024];   // 16MB
__device__ __half d_x16 [(size_t)NUM_T * 1024];          // 4MB
__device__ __half d_inter[(size_t)NROWS * 1024];         // 8MB
__device__ float  d_y   [(size_t)NROWS * 1024];          // 16MB (gemm2 per-row out)

// ---------------- ptx helpers ----------------
__device__ __forceinline__ uint32_t smem_u32(const void* p) {
    uint32_t a;
    asm("{ .reg .u64 t; cvta.to.shared.u64 t, %1; cvt.u32.u64 %0, t; }" : "=r"(a) : "l"(p));
    return a;
}
__device__ __forceinline__ void cpa16(uint32_t dst, const void* src, uint32_t srcbytes) {
    asm volatile("cp.async.cg.shared.global [%0], [%1], 16, %2;"
                 :: "r"(dst), "l"(src), "r"(srcbytes));
}
__device__ __forceinline__ void cpa_commit() { asm volatile("cp.async.commit_group;" ::: "memory"); }
__device__ __forceinline__ void ldsm_x4(uint32_t* r, uint32_t addr) {
    asm volatile("ldmatrix.sync.aligned.m8n8.x4.shared.b16 {%0,%1,%2,%3}, [%4];"
                 : "=r"(r[0]), "=r"(r[1]), "=r"(r[2]), "=r"(r[3]) : "r"(addr));
}
__device__ __forceinline__ void ldsm_x4t(uint32_t* r, uint32_t addr) {
    asm volatile("ldmatrix.sync.aligned.m8n8.x4.trans.shared.b16 {%0,%1,%2,%3}, [%4];"
                 : "=r"(r[0]), "=r"(r[1]), "=r"(r[2]), "=r"(r[3]) : "r"(addr));
}
__device__ __forceinline__ void hmma(float* c, const uint32_t* a, const uint32_t* b) {
    asm volatile(
        "mma.sync.aligned.m16n8k16.row.col.f32.f16.f16.f32 "
        "{%0,%1,%2,%3}, {%4,%5,%6,%7}, {%8,%9}, {%0,%1,%2,%3};"
        : "+f"(c[0]), "+f"(c[1]), "+f"(c[2]), "+f"(c[3])
        : "r"(a[0]), "r"(a[1]), "r"(a[2]), "r"(a[3]), "r"(b[0]), "r"(b[1]));
}

// ---------------- prep: fp32 -> fp16 (w13 column-interleaved) ----------------
__device__ __forceinline__ uint2 pack4(float4 v) {
    __half2 p0 = __halves2half2(__float2half_rn(v.x), __float2half_rn(v.y));
    __half2 p1 = __halves2half2(__float2half_rn(v.z), __float2half_rn(v.w));
    uint2 h;
    h.x = *reinterpret_cast<uint32_t*>(&p0);
    h.y = *reinterpret_cast<uint32_t*>(&p1);
    return h;
}

__global__ void prep_kernel(const float* __restrict__ x, const float* __restrict__ w13,
                            const float* __restrict__ w2) {
    const int stride = gridDim.x * blockDim.x;
    const int tid = blockIdx.x * blockDim.x + threadIdx.x;
    // w13 with gate/up interleave: src col c -> dest col
    //   c < 1024 (gate): (c>>6)*128 + (c&63)
    //   c >= 1024 (up) : ((c-1024)>>6)*128 + 64 + ((c-1024)&63)
    for (int i = tid; i < (NUM_E * 1024 * 2048) / 4; i += stride) {
        float4 v = reinterpret_cast<const float4*>(w13)[i];
        int f = i * 4;
        int c = f & 2047;
        size_t rowbase = (size_t)(f >> 11) * 2048;
        int dc = (c < 1024) ? ((c >> 6) * 128 + (c & 63))
                            : (((c - 1024) >> 6) * 128 + 64 + ((c - 1024) & 63));
        *reinterpret_cast<uint2*>(d_w13h + rowbase + dc) = pack4(v);
    }
    for (int i = tid; i < (NUM_E * 1024 * 1024) / 4; i += stride) {
        float4 v = reinterpret_cast<const float4*>(w2)[i];
        reinterpret_cast<uint2*>(d_w2h)[i] = pack4(v);
    }
    for (int i = tid; i < (NUM_T * 1024) / 4; i += stride) {
        float4 v = reinterpret_cast<const float4*>(x)[i];
        reinterpret_cast<uint2*>(d_x16)[i] = pack4(v);
    }
}

// ---------------- routing: single block does top2 + scan + assign ----------------
__global__ void route_all(const float* __restrict__ logits) {
    __shared__ int cnt[NUM_E], off[NUM_E], cur[NUM_E];
    const int tx = threadIdx.x;   // 1024 threads, 2 tokens each
    if (tx < NUM_E) { cnt[tx] = 0; cur[tx] = 0; }
    __syncthreads();
    int ids[2][2];
#pragma unroll
    for (int u = 0; u < 2; u++) {
        int t = tx + u * 1024;
        float l[NUM_E];
#pragma unroll
        for (int e = 0; e < NUM_E; e++) l[e] = logits[t * NUM_E + e];
        int i0 = 0; float v0 = l[0];
#pragma unroll
        for (int e = 1; e < NUM_E; e++) if (l[e] > v0) { v0 = l[e]; i0 = e; }
        int i1 = -1; float v1 = -1e30f;
#pragma unroll
        for (int e = 0; e < NUM_E; e++) if (e != i0 && l[e] > v1) { v1 = l[e]; i1 = e; }
        float z  = expf(v1 - v0);
        float w0 = 1.0f / (1.0f + z);
        d_topk_w[t * 2] = w0;
        d_topk_w[t * 2 + 1] = 1.0f - w0;
        ids[u][0] = i0; ids[u][1] = i1;
        atomicAdd(&cnt[i0], 1);
        atomicAdd(&cnt[i1], 1);
    }
    __syncthreads();
    if (tx == 0) {
        int s = 0;
#pragma unroll
        for (int e = 0; e < NUM_E; e++) {
            off[e] = s; d_offset[e] = s; d_count[e] = cnt[e]; s += cnt[e];
        }
        d_offset[NUM_E] = s;
    }
    __syncthreads();
#pragma unroll
    for (int u = 0; u < 2; u++) {
        int t = tx + u * 1024;
#pragma unroll
        for (int k = 0; k < 2; k++) {
            int e = ids[u][k];
            int pos = atomicAdd(&cur[e], 1);
            int row = off[e] + pos;
            d_row_token[row] = t;
            d_tok_row[t * 2 + k] = row;
        }
    }
}

// ---------------- grouped GEMM ----------------
// G2=false: acc = x16[token(row)] @ w13h[e] (interleaved);  epilogue: silu(g)*u -> d_inter fp16
// G2=true : acc = d_inter[row] @ w2h[e];                    epilogue: d_y[row] = acc
template <bool G2, int NGLOB>
__global__ void __launch_bounds__(256, 2) gemm_cl() {
    extern __shared__ __align__(128) char smem[];
    const uint32_t sb = smem_u32(smem);
    const int tid = threadIdx.x, wid = tid >> 5, lane = tid & 31;

    const int e   = blockIdx.y >> 4;
    const int mt  = blockIdx.y & 15;
    const int cnt = d_count[e];
    const int m0  = mt * BM;
    if (m0 >= cnt) return;
    const int off  = d_offset[e];
    const int n0   = blockIdx.x * BN;
    const int row0 = off + m0;

    const __half* Bw = (G2 ? d_w2h : d_w13h) + (size_t)e * 1024 * NGLOB;

    const int r0a = tid >> 2;
    const int s0  = tid & 3;
    const bool v0 = (m0 + r0a) < cnt;
    const bool v1 = (m0 + r0a + 64) < cnt;
    const __half *Arow0, *Arow1;
    if (G2) {
        int g0 = min(row0 + r0a, NROWS - 1);
        int g1 = min(row0 + r0a + 64, NROWS - 1);
        Arow0 = d_inter + (size_t)g0 * 1024;
        Arow1 = d_inter + (size_t)g1 * 1024;
    } else {
        int g0 = v0 ? d_row_token[row0 + r0a] : 0;
        int g1 = v1 ? d_row_token[row0 + r0a + 64] : 0;
        Arow0 = d_x16 + (size_t)g0 * 1024;
        Arow1 = d_x16 + (size_t)g1 * 1024;
    }
    const int kr0 = tid >> 4;
    const int sB  = tid & 15;

    auto load_stage = [&](int stg, int k0) {
        uint32_t base = sb + (uint32_t)stg * STAGE_BYTES;
        uint32_t da = base + (uint32_t)(r0a * 80 + s0 * 16);
        cpa16(da,            Arow0 + k0 + s0 * 8, v0 ? 16u : 0u);
        cpa16(da + 64 * 80,  Arow1 + k0 + s0 * 8, v1 ? 16u : 0u);
        uint32_t db = base + A_BYTES + (uint32_t)(kr0 * 272 + sB * 16);
        cpa16(db,             Bw + (size_t)(k0 + kr0) * NGLOB + n0 + sB * 8, 16u);
        cpa16(db + 16 * 272,  Bw + (size_t)(k0 + kr0 + 16) * NGLOB + n0 + sB * 8, 16u);
    };

    const int warpM = (wid >> 2) * 64;
    const int warpN = (wid & 3) * 32;

    float acc[4][4][4];
#pragma unroll
    for (int i = 0; i < 4; i++)
#pragma unroll
        for (int j = 0; j < 4; j++)
#pragma unroll
            for (int q = 0; q < 4; q++) acc[i][j][q] = 0.f;

    const int a_row = lane & 15;
    const int a_col = (lane >> 4) << 3;
    const int b_row = (lane & 7) + (((lane >> 3) & 1) << 3);
    const int b_col = (lane >> 4) << 3;

#pragma unroll
    for (int s = 0; s < STAGES - 1; s++) { load_stage(s, s * BK); cpa_commit(); }

    for (int kt = 0; kt < KTILES; kt++) {
        asm volatile("cp.async.wait_group %0;" :: "n"(STAGES - 2));
        __syncthreads();
        int nk = kt + STAGES - 1;
        if (nk < KTILES) load_stage(nk & (STAGES - 1), nk * BK);
        cpa_commit();

        uint32_t As = sb + (uint32_t)(kt & (STAGES - 1)) * STAGE_BYTES;
        uint32_t Bs = As + A_BYTES;
#pragma unroll
        for (int kk = 0; kk < BK; kk += 16) {
            uint32_t af[4][4], bt[2][4];
#pragma unroll
            for (int i = 0; i < 4; i++)
                ldsm_x4(af[i], As + (uint32_t)((warpM + i * 16 + a_row) * 80 + (kk + a_col) * 2));
#pragma unroll
            for (int j2 = 0; j2 < 2; j2++)
                ldsm_x4t(bt[j2], Bs + (uint32_t)((kk + b_row) * 272 + (warpN + j2 * 16 + b_col) * 2));
#pragma unroll
            for (int i = 0; i < 4; i++)
#pragma unroll
                for (int j = 0; j < 4; j++)
                    hmma(acc[i][j], af[i], &bt[j >> 1][(j & 1) * 2]);
        }
    }

    // ---------------- epilogue ----------------
    const int gq = lane >> 2, tg = lane & 3;
    if (!G2) {
        // stage acc in smem, fuse swiglu, write fp16 inter (cols n-tile*64 .. +64)
        asm volatile("cp.async.wait_group 0;" ::: "memory");
        __syncthreads();                       // done with stage buffers
        float* S = reinterpret_cast<float*>(smem);   // [128][132]
#pragma unroll
        for (int i = 0; i < 4; i++) {
            int rlo = warpM + i * 16 + gq;
#pragma unroll
            for (int j = 0; j < 4; j++) {
                int c = warpN + j * 8 + 2 * tg;
                *reinterpret_cast<float2*>(&S[rlo * 132 + c]) =
                    make_float2(acc[i][j][0], acc[i][j][1]);
                *reinterpret_cast<float2*>(&S[(rlo + 8) * 132 + c]) =
                    make_float2(acc[i][j][2], acc[i][j][3]);
            }
        }
        __syncthreads();
        const int jj = (tid & 15) * 4;
        const int icol = blockIdx.x * 64 + jj;
#pragma unroll
        for (int p = 0; p < 8; p++) {
            int r = (tid >> 4) + p * 16;
            if (m0 + r < cnt) {
                float4 g = *reinterpret_cast<float4*>(&S[r * 132 + jj]);
                float4 u = *reinterpret_cast<float4*>(&S[r * 132 + 64 + jj]);
                float o0 = g.x / (1.f + expf(-g.x)) * u.x;
                float o1 = g.y / (1.f + expf(-g.y)) * u.y;
                float o2 = g.z / (1.f + expf(-g.z)) * u.z;
                float o3 = g.w / (1.f + expf(-g.w)) * u.w;
                *reinterpret_cast<uint2*>(d_inter + (size_t)(row0 + r) * 1024 + icol) =
                    pack4(make_float4(o0, o1, o2, o3));
            }
        }
    } else {
        // plain store of per-row result (weights applied in finalize)
#pragma unroll
        for (int i = 0; i < 4; i++) {
            int mlo = warpM + i * 16 + gq;
            int mhi = mlo + 8;
#pragma unroll
            for (int j = 0; j < 4; j++) {
                int c = n0 + warpN + j * 8 + 2 * tg;
                if (m0 + mlo < cnt)
                    *reinterpret_cast<float2*>(d_y + (size_t)(row0 + mlo) * 1024 + c) =
                        make_float2(acc[i][j][0], acc[i][j][1]);
                if (m0 + mhi < cnt)
                    *reinterpret_cast<float2*>(d_y + (size_t)(row0 + mhi) * 1024 + c) =
                        make_float2(acc[i][j][2], acc[i][j][3]);
            }
        }
    }
}

// ---------------- finalize: out[t] = w0*y[r0] + w1*y[r1] ----------------
__global__ void finalize_kernel(float* __restrict__ out) {
    int t = blockIdx.x;
    int c = threadIdx.x * 4;
    int r0 = d_tok_row[t * 2], r1 = d_tok_row[t * 2 + 1];
    float w0 = d_topk_w[t * 2], w1 = d_topk_w[t * 2 + 1];
    float4 a = *reinterpret_cast<const float4*>(d_y + (size_t)r0 * 1024 + c);
    float4 b = *reinterpret_cast<const float4*>(d_y + (size_t)r1 * 1024 + c);
    float4 o;
    o.x = w0 * a.x + w1 * b.x;
    o.y = w0 * a.y + w1 * b.y;
    o.z = w0 * a.z + w1 * b.z;
    o.w = w0 * a.w + w1 * b.w;
    *reinterpret_cast<float4*>(out + (size_t)t * NUM_H + c) = o;
}

// ---------------- launch ----------------
extern "C" void kernel_launch(void* const* d_in, const int* in_sizes, int n_in,
                              void* d_out, int out_size) {
    const float* x      = (const float*)d_in[0];
    const float* logits = (const float*)d_in[1];
    const float* w13    = (const float*)d_in[2];
    const float* w2     = (const float*)d_in[3];
    float* out = (float*)d_out;

    cudaFuncSetAttribute(gemm_cl<false, 2048>, cudaFuncAttributeMaxDynamicSharedMemorySize, SMEM_GEMM);
    cudaFuncSetAttribute(gemm_cl<true, 1024>,  cudaFuncAttributeMaxDynamicSharedMemorySize, SMEM_GEMM);

    prep_kernel<<<1024, 256>>>(x, w13, w2);
    route_all<<<1, 1024>>>(logits);
    gemm_cl<false, 2048><<<dim3(2048 / BN, NUM_E * 16), 256, SMEM_GEMM>>>();
    gemm_cl<true, 1024><<<dim3(1024 / BN, NUM_E * 16), 256, SMEM_GEMM>>>();
    finalize_kernel<<<NUM_T, 256>>>(out);
}